// round 11
// baseline (speedup 1.0000x reference)
#include <cuda_runtime.h>
#include <cuda_fp16.h>
#include <cstdint>

// ---------------------------------------------------------------------------
// EdgeBlock: 4-layer MLP (512->256->256->256->128) per edge, segment mean over
// ei (1024 segments), gather means back per edge.
//
// FP16 compute (10 mantissa bits): weight-rounding error is correlated across
// the segment mean (doesn't average out), so weights need fp16, not bf16.
//
// Pipeline (5 launches, all graph-capturable):
//   1. prep_kernel    : convert W1..W4 fp32->fp16 into g_Wb, zero sums/counts
//   2. count_kernel   : histogram ei -> g_cnts (float)
//   3. mlp_kernel     : fused 4-layer fp16 tensor-core MLP per 128-edge tile,
//                       L4 output reduced into g_sums via red.global.add.v4.f32
//   4. means_kernel   : g_means = g_sums / g_cnts
//   5. gather_kernel  : out[i] = g_means[ei[i]]
// ---------------------------------------------------------------------------

#define NSEG   1024
#define FEAT   128
#define D_IN   512
#define HID    256

// weight offsets in elements within g_Wb
#define OFF_W1 0
#define OFF_W2 131072           // 512*256
#define OFF_W3 196608           // + 256*256
#define OFF_W4 262144           // + 256*256
#define W_TOTAL 294912          // + 256*128

__device__ __half g_Wb[W_TOTAL];
__device__ float g_sums[NSEG * FEAT];
__device__ float g_cnts[NSEG];
__device__ float g_means[NSEG * FEAT];

// ---------------- PTX helpers ----------------
__device__ __forceinline__ uint32_t smem_u32(const void* p) {
    return (uint32_t)__cvta_generic_to_shared(p);
}
__device__ __forceinline__ void ldsm4(uint32_t* d, uint32_t addr) {
    asm volatile("ldmatrix.sync.aligned.m8n8.x4.shared.b16 {%0,%1,%2,%3}, [%4];"
                 : "=r"(d[0]), "=r"(d[1]), "=r"(d[2]), "=r"(d[3]) : "r"(addr));
}
__device__ __forceinline__ void ldsm4t(uint32_t* d, uint32_t addr) {
    asm volatile("ldmatrix.sync.aligned.m8n8.x4.trans.shared.b16 {%0,%1,%2,%3}, [%4];"
                 : "=r"(d[0]), "=r"(d[1]), "=r"(d[2]), "=r"(d[3]) : "r"(addr));
}
__device__ __forceinline__ void mma16816(float* d, const uint32_t* a, const uint32_t* b) {
    asm volatile("mma.sync.aligned.m16n8k16.row.col.f32.f16.f16.f32 "
                 "{%0,%1,%2,%3}, {%4,%5,%6,%7}, {%8,%9}, {%0,%1,%2,%3};"
                 : "+f"(d[0]), "+f"(d[1]), "+f"(d[2]), "+f"(d[3])
                 : "r"(a[0]), "r"(a[1]), "r"(a[2]), "r"(a[3]),
                   "r"(b[0]), "r"(b[1]));
}
__device__ __forceinline__ void red4(float* p, float4 v) {
    asm volatile("red.global.add.v4.f32 [%0], {%1,%2,%3,%4};"
                 :: "l"(p), "f"(v.x), "f"(v.y), "f"(v.z), "f"(v.w) : "memory");
}
__device__ __forceinline__ uint32_t h2_bits(__half2 h) {
    return *reinterpret_cast<uint32_t*>(&h);
}

// SMEM layout (dynamic): activations A at [0, 131072), weight panel B at
// [131072, 163840). L4 fp32 staging reuses A's first 64 KB.
#define A_BYTES 131072
#define B_OFF   131072
#define SMEM_BYTES 163840

// ---------------------------------------------------------------------------
// Warp-tiled GEMM: M=128 (tile rows, in swizzled smem A, row stride rowBA),
// NTILE columns (weights [K][NTILE] fp16 row-major in global, streamed in
// 64-row panels to smem B), fp32 acc in registers.
// 8 warps: wm = wid>>2 (2 x 64 rows), wn = wid&3 (4 x NTILE/4 cols).
// NF = n-fragments per warp = NTILE/32.
// ---------------------------------------------------------------------------
template <int NTILE, int NF>
__device__ __forceinline__ void run_gemm(
    const __half* __restrict__ Wg, int K,
    char* Asp, int rowBA, char* Bsp, float* acc)
{
    const int tid  = threadIdx.x;
    const int lane = tid & 31;
    const int wid  = tid >> 5;
    const int wm   = wid >> 2;
    const int wn   = wid & 3;
    constexpr int BROWB = NTILE * 2;

    const uint32_t As = smem_u32(Asp);
    const uint32_t Bs = smem_u32(Bsp);

#pragma unroll
    for (int i = 0; i < 4 * NF * 4; i++) acc[i] = 0.f;

    for (int k0 = 0; k0 < K; k0 += 64) {
        __syncthreads();   // previous panel's reads (and prior A writes) done
        // ---- load 64 x NTILE fp16 weight panel into swizzled smem ----
        {
            constexpr int CHUNKS = 64 * NTILE / 8;      // 16B chunks
            const uint4* src = reinterpret_cast<const uint4*>(Wg + (size_t)k0 * NTILE);
#pragma unroll
            for (int i = 0; i < CHUNKS / 256; i++) {
                int idx = tid + i * 256;
                int kr  = idx / (NTILE / 8);
                int cc  = idx % (NTILE / 8);
                uint4 v = src[idx];
                uint32_t byte = (uint32_t)(kr * BROWB + cc * 16) ^ ((kr & 7) << 4);
                *reinterpret_cast<uint4*>(Bsp + byte) = v;
            }
        }
        __syncthreads();

#pragma unroll
        for (int kk = 0; kk < 64; kk += 16) {
            // ---- A fragments: 4 x m16k16 ----
            uint32_t a[4][4];
#pragma unroll
            for (int mf = 0; mf < 4; mf++) {
                int r = wm * 64 + mf * 16 + (lane & 15);
                uint32_t byte = (uint32_t)(r * rowBA + (((k0 + kk) >> 3) + (lane >> 4)) * 16);
                byte ^= (r & 7) << 4;
                ldsm4(a[mf], As + byte);
            }
            // ---- B fragments: NF x k16n8 via NF/2 trans loads ----
            uint32_t b[NF][2];
            {
                const int within = lane & 7;
                const int mat    = lane >> 3;
                const int kr     = kk + within + ((mat & 1) << 3);
                const uint32_t rowbase = (uint32_t)(kr * BROWB) ^ ((kr & 7) << 4);
#pragma unroll
                for (int p = 0; p < NF / 2; p++) {
                    int chunk = wn * NF + p * 2 + (mat >> 1);
                    uint32_t t[4];
                    ldsm4t(t, Bs + (rowbase ^ (uint32_t)(chunk * 16)));
                    b[2 * p][0] = t[0]; b[2 * p][1] = t[1];
                    b[2 * p + 1][0] = t[2]; b[2 * p + 1][1] = t[3];
                }
            }
#pragma unroll
            for (int mf = 0; mf < 4; mf++)
#pragma unroll
                for (int nf = 0; nf < NF; nf++)
                    mma16816(acc + (mf * NF + nf) * 4, a[mf], b[nf]);
        }
    }
    __syncthreads();   // all warps done reading A before epilogue overwrites it
}

// bias + relu epilogue -> fp16 into A (width 256, rowB=512), swizzled
__device__ __forceinline__ void epilogue_relu(
    const float* acc, const float* __restrict__ bias, char* Asp)
{
    const int tid = threadIdx.x, lane = tid & 31, wid = tid >> 5;
    const int wm = wid >> 2, wn = wid & 3;
#pragma unroll
    for (int nf = 0; nf < 8; nf++) {
        int c = wn * 64 + nf * 8 + (lane & 3) * 2;
        float b0 = __ldg(bias + c), b1 = __ldg(bias + c + 1);
#pragma unroll
        for (int mf = 0; mf < 4; mf++) {
            const float* d = acc + (mf * 8 + nf) * 4;
            int r0 = wm * 64 + mf * 16 + (lane >> 2);
            int r1 = r0 + 8;
            float x0 = fmaxf(d[0] + b0, 0.f), x1 = fmaxf(d[1] + b1, 0.f);
            float x2 = fmaxf(d[2] + b0, 0.f), x3 = fmaxf(d[3] + b1, 0.f);
            __half2 p0 = __float22half2_rn(make_float2(x0, x1));
            __half2 p1 = __float22half2_rn(make_float2(x2, x3));
            uint32_t by0 = (uint32_t)(r0 * 512 + c * 2) ^ ((r0 & 7) << 4);
            uint32_t by1 = (uint32_t)(r1 * 512 + c * 2) ^ ((r1 & 7) << 4);
            *reinterpret_cast<uint32_t*>(Asp + by0) = h2_bits(p0);
            *reinterpret_cast<uint32_t*>(Asp + by1) = h2_bits(p1);
        }
    }
}

// ---------------------------------------------------------------------------
__global__ void __launch_bounds__(256, 1) mlp_kernel(
    const float* __restrict__ g,  const float* __restrict__ ns,
    const float* __restrict__ nr, const float* __restrict__ e,
    const int*   __restrict__ ei,
    const float* __restrict__ b1, const float* __restrict__ b2,
    const float* __restrict__ b3, const float* __restrict__ b4,
    int nEdges)
{
    extern __shared__ __align__(16) char smem[];
    char* Asp = smem;
    char* Bsp = smem + B_OFF;

    const int tid = threadIdx.x;
    const int m0  = blockIdx.x * 128;

    // ---- stage inputs: 128 rows x 512 fp16 (concat g|ns|nr|e), swizzled ----
#pragma unroll 4
    for (int i = 0; i < 32; i++) {
        int idx = tid + i * 256;           // 0..8191 chunk index
        int r   = idx >> 6;                // row 0..127
        int cc  = idx & 63;                // 16B chunk within row
        uint32_t byte = ((uint32_t)(r << 10) + (uint32_t)(cc << 4)) ^ ((r & 7) << 4);
        uint4 out4;
        int edge = m0 + r;
        if (edge < nEdges) {
            const float* base = (cc < 32) ? ((cc < 16) ? g : ns)
                                          : ((cc < 48) ? nr : e);
            int col0 = (cc & 15) << 3;
            const float4* p = reinterpret_cast<const float4*>(base + (size_t)edge * 128 + col0);
            float4 v0 = p[0], v1 = p[1];
            out4.x = h2_bits(__float22half2_rn(make_float2(v0.x, v0.y)));
            out4.y = h2_bits(__float22half2_rn(make_float2(v0.z, v0.w)));
            out4.z = h2_bits(__float22half2_rn(make_float2(v1.x, v1.y)));
            out4.w = h2_bits(__float22half2_rn(make_float2(v1.z, v1.w)));
        } else {
            out4 = make_uint4(0, 0, 0, 0);
        }
        *reinterpret_cast<uint4*>(Asp + byte) = out4;
    }
    // (run_gemm opens with __syncthreads)

    float acc[128];

    run_gemm<256, 8>(g_Wb + OFF_W1, 512, Asp, 1024, Bsp, acc);
    epilogue_relu(acc, b1, Asp);
    run_gemm<256, 8>(g_Wb + OFF_W2, 256, Asp, 512, Bsp, acc);
    epilogue_relu(acc, b2, Asp);
    run_gemm<256, 8>(g_Wb + OFF_W3, 256, Asp, 512, Bsp, acc);
    epilogue_relu(acc, b3, Asp);
    run_gemm<128, 4>(g_Wb + OFF_W4, 256, Asp, 512, Bsp, acc);

    // ---- L4 epilogue: +b4 (no relu), stage fp32 to smem (swizzled 16B) ----
    {
        const int lane = tid & 31, wid = tid >> 5;
        const int wm = wid >> 2, wn = wid & 3;
#pragma unroll
        for (int nf = 0; nf < 4; nf++) {
            int c = wn * 32 + nf * 8 + (lane & 3) * 2;
            float b0 = __ldg(b4 + c), b1v = __ldg(b4 + c + 1);
#pragma unroll
            for (int mf = 0; mf < 4; mf++) {
                const float* d = acc + (mf * 4 + nf) * 4;
                int r0 = wm * 64 + mf * 16 + (lane >> 2);
                int r1 = r0 + 8;
                uint32_t by0 = (uint32_t)(r0 * 512 + c * 4) ^ ((r0 & 7) << 4);
                uint32_t by1 = (uint32_t)(r1 * 512 + c * 4) ^ ((r1 & 7) << 4);
                *reinterpret_cast<float2*>(Asp + by0) = make_float2(d[0] + b0, d[1] + b1v);
                *reinterpret_cast<float2*>(Asp + by1) = make_float2(d[2] + b0, d[3] + b1v);
            }
        }
    }
    __syncthreads();

    // ---- vector-red segment sums: thread t handles row t/2, half t&1 ----
    {
        int lr   = tid >> 1;
        int half = tid & 1;
        int edge = m0 + lr;
        if (edge < nEdges) {
            int seg = ei[edge];
            float* dst = g_sums + (size_t)seg * FEAT + half * 64;
#pragma unroll
            for (int j = 0; j < 16; j++) {
                int c = half * 64 + j * 4;
                uint32_t byte = (uint32_t)(lr * 512 + c * 4) ^ ((lr & 7) << 4);
                float4 v = *reinterpret_cast<float4*>(Asp + byte);
                red4(dst + j * 4, v);
            }
        }
    }
}

// ---------------------------------------------------------------------------
__global__ void prep_kernel(const float* __restrict__ W1, const float* __restrict__ W2,
                            const float* __restrict__ W3, const float* __restrict__ W4)
{
    int i = blockIdx.x * blockDim.x + threadIdx.x;
    int stride = gridDim.x * blockDim.x;
    for (int idx = i; idx < W_TOTAL; idx += stride) {
        float v;
        if (idx < OFF_W2)      v = W1[idx];
        else if (idx < OFF_W3) v = W2[idx - OFF_W2];
        else if (idx < OFF_W4) v = W3[idx - OFF_W3];
        else                   v = W4[idx - OFF_W4];
        g_Wb[idx] = __float2half_rn(v);
    }
    for (int idx = i; idx < NSEG * FEAT; idx += stride) g_sums[idx] = 0.f;
    for (int idx = i; idx < NSEG; idx += stride) g_cnts[idx] = 0.f;
}

__global__ void count_kernel(const int* __restrict__ ei, int nEdges)
{
    int i = blockIdx.x * blockDim.x + threadIdx.x;
    if (i < nEdges) atomicAdd(&g_cnts[ei[i]], 1.0f);
}

__global__ void means_kernel()
{
    int i = blockIdx.x * blockDim.x + threadIdx.x;  // 131072 threads exactly
    g_means[i] = g_sums[i] / g_cnts[i >> 7];
}

__global__ void gather_kernel(const int* __restrict__ ei, float* __restrict__ out, int nEdges)
{
    int i = blockIdx.x * blockDim.x + threadIdx.x;   // one float4 per thread
    int total = nEdges * 32;
    if (i < total) {
        int edge = i >> 5;
        int c4   = i & 31;
        int seg  = __ldg(ei + edge);
        float4 v = *reinterpret_cast<const float4*>(g_means + (size_t)seg * FEAT + c4 * 4);
        reinterpret_cast<float4*>(out)[i] = v;
    }
}

// ---------------------------------------------------------------------------
extern "C" void kernel_launch(void* const* d_in, const int* in_sizes, int n_in,
                              void* d_out, int out_size)
{
    const float* g  = (const float*)d_in[0];
    const float* ns = (const float*)d_in[1];
    const float* nr = (const float*)d_in[2];
    const float* e  = (const float*)d_in[3];
    const int*   ei = (const int*)  d_in[4];
    const float* W1 = (const float*)d_in[5];
    const float* b1 = (const float*)d_in[6];
    const float* W2 = (const float*)d_in[7];
    const float* b2 = (const float*)d_in[8];
    const float* W3 = (const float*)d_in[9];
    const float* b3 = (const float*)d_in[10];
    const float* W4 = (const float*)d_in[11];
    const float* b4 = (const float*)d_in[12];
    float* out = (float*)d_out;

    const int nEdges = in_sizes[4];

    cudaFuncSetAttribute(mlp_kernel, cudaFuncAttributeMaxDynamicSharedMemorySize, SMEM_BYTES);

    prep_kernel<<<1152, 256>>>(W1, W2, W3, W4);
    count_kernel<<<(nEdges + 255) / 256, 256>>>(ei, nEdges);
    mlp_kernel<<<(nEdges + 127) / 128, 256, SMEM_BYTES>>>(g, ns, nr, e, ei,
                                                          b1, b2, b3, b4, nEdges);
    means_kernel<<<(NSEG * FEAT) / 256, 256>>>();
    gather_kernel<<<(nEdges * 32 + 255) / 256, 256>>>(ei, out, nEdges);
}

// round 12
// speedup vs baseline: 1.0002x; 1.0002x over previous
#include <cuda_runtime.h>
#include <cuda_fp16.h>
#include <cstdint>

// ---------------------------------------------------------------------------
// EdgeBlock: 4-layer MLP (512->256->256->256->128) per edge, segment mean over
// ei (1024 segments), gather means back per edge.
//
// FP16 compute (10 mantissa bits): weight-rounding error is correlated across
// the segment mean (doesn't average out), so weights need fp16, not bf16.
//
// Pipeline (5 launches, all graph-capturable):
//   1. prep_kernel    : convert W1..W4 fp32->fp16 into g_Wb, zero sums/counts
//   2. count_kernel   : histogram ei -> g_cnts (float)
//   3. mlp_kernel     : fused 4-layer fp16 tensor-core MLP per 128-edge tile,
//                       L4 output reduced into g_sums via red.global.add.v4.f32
//   4. means_kernel   : g_means = g_sums / g_cnts
//   5. gather_kernel  : out[i] = g_means[ei[i]]
// ---------------------------------------------------------------------------

#define NSEG   1024
#define FEAT   128
#define D_IN   512
#define HID    256

// weight offsets in elements within g_Wb
#define OFF_W1 0
#define OFF_W2 131072           // 512*256
#define OFF_W3 196608           // + 256*256
#define OFF_W4 262144           // + 256*256
#define W_TOTAL 294912          // + 256*128

__device__ __half g_Wb[W_TOTAL];
__device__ float g_sums[NSEG * FEAT];
__device__ float g_cnts[NSEG];
__device__ float g_means[NSEG * FEAT];

// ---------------- PTX helpers ----------------
__device__ __forceinline__ uint32_t smem_u32(const void* p) {
    return (uint32_t)__cvta_generic_to_shared(p);
}
__device__ __forceinline__ void ldsm4(uint32_t* d, uint32_t addr) {
    asm volatile("ldmatrix.sync.aligned.m8n8.x4.shared.b16 {%0,%1,%2,%3}, [%4];"
                 : "=r"(d[0]), "=r"(d[1]), "=r"(d[2]), "=r"(d[3]) : "r"(addr));
}
__device__ __forceinline__ void ldsm4t(uint32_t* d, uint32_t addr) {
    asm volatile("ldmatrix.sync.aligned.m8n8.x4.trans.shared.b16 {%0,%1,%2,%3}, [%4];"
                 : "=r"(d[0]), "=r"(d[1]), "=r"(d[2]), "=r"(d[3]) : "r"(addr));
}
__device__ __forceinline__ void mma16816(float* d, const uint32_t* a, const uint32_t* b) {
    asm volatile("mma.sync.aligned.m16n8k16.row.col.f32.f16.f16.f32 "
                 "{%0,%1,%2,%3}, {%4,%5,%6,%7}, {%8,%9}, {%0,%1,%2,%3};"
                 : "+f"(d[0]), "+f"(d[1]), "+f"(d[2]), "+f"(d[3])
                 : "r"(a[0]), "r"(a[1]), "r"(a[2]), "r"(a[3]),
                   "r"(b[0]), "r"(b[1]));
}
__device__ __forceinline__ void red4(float* p, float4 v) {
    asm volatile("red.global.add.v4.f32 [%0], {%1,%2,%3,%4};"
                 :: "l"(p), "f"(v.x), "f"(v.y), "f"(v.z), "f"(v.w) : "memory");
}
__device__ __forceinline__ uint32_t h2_bits(__half2 h) {
    return *reinterpret_cast<uint32_t*>(&h);
}

// SMEM layout (dynamic): activations A at [0, 131072), weight panel B at
// [131072, 163840). L4 fp32 staging reuses A's first 64 KB.
#define A_BYTES 131072
#define B_OFF   131072
#define SMEM_BYTES 163840

// ---------------------------------------------------------------------------
// Warp-tiled GEMM: M=128 (tile rows, in swizzled smem A, row stride rowBA),
// NTILE columns (weights [K][NTILE] fp16 row-major in global, streamed in
// 64-row panels to smem B), fp32 acc in registers.
// 8 warps: wm = wid>>2 (2 x 64 rows), wn = wid&3 (4 x NTILE/4 cols).
// NF = n-fragments per warp = NTILE/32.
// ---------------------------------------------------------------------------
template <int NTILE, int NF>
__device__ __forceinline__ void run_gemm(
    const __half* __restrict__ Wg, int K,
    char* Asp, int rowBA, char* Bsp, float* acc)
{
    const int tid  = threadIdx.x;
    const int lane = tid & 31;
    const int wid  = tid >> 5;
    const int wm   = wid >> 2;
    const int wn   = wid & 3;
    constexpr int BROWB = NTILE * 2;

    const uint32_t As = smem_u32(Asp);
    const uint32_t Bs = smem_u32(Bsp);

#pragma unroll
    for (int i = 0; i < 4 * NF * 4; i++) acc[i] = 0.f;

    for (int k0 = 0; k0 < K; k0 += 64) {
        __syncthreads();   // previous panel's reads (and prior A writes) done
        // ---- load 64 x NTILE fp16 weight panel into swizzled smem ----
        {
            constexpr int CHUNKS = 64 * NTILE / 8;      // 16B chunks
            const uint4* src = reinterpret_cast<const uint4*>(Wg + (size_t)k0 * NTILE);
#pragma unroll
            for (int i = 0; i < CHUNKS / 256; i++) {
                int idx = tid + i * 256;
                int kr  = idx / (NTILE / 8);
                int cc  = idx % (NTILE / 8);
                uint4 v = src[idx];
                uint32_t byte = (uint32_t)(kr * BROWB + cc * 16) ^ ((kr & 7) << 4);
                *reinterpret_cast<uint4*>(Bsp + byte) = v;
            }
        }
        __syncthreads();

#pragma unroll
        for (int kk = 0; kk < 64; kk += 16) {
            // ---- A fragments: 4 x m16k16 ----
            uint32_t a[4][4];
#pragma unroll
            for (int mf = 0; mf < 4; mf++) {
                int r = wm * 64 + mf * 16 + (lane & 15);
                uint32_t byte = (uint32_t)(r * rowBA + (((k0 + kk) >> 3) + (lane >> 4)) * 16);
                byte ^= (r & 7) << 4;
                ldsm4(a[mf], As + byte);
            }
            // ---- B fragments: NF x k16n8 via NF/2 trans loads ----
            uint32_t b[NF][2];
            {
                const int within = lane & 7;
                const int mat    = lane >> 3;
                const int kr     = kk + within + ((mat & 1) << 3);
                const uint32_t rowbase = (uint32_t)(kr * BROWB) ^ ((kr & 7) << 4);
#pragma unroll
                for (int p = 0; p < NF / 2; p++) {
                    int chunk = wn * NF + p * 2 + (mat >> 1);
                    uint32_t t[4];
                    ldsm4t(t, Bs + (rowbase ^ (uint32_t)(chunk * 16)));
                    b[2 * p][0] = t[0]; b[2 * p][1] = t[1];
                    b[2 * p + 1][0] = t[2]; b[2 * p + 1][1] = t[3];
                }
            }
#pragma unroll
            for (int mf = 0; mf < 4; mf++)
#pragma unroll
                for (int nf = 0; nf < NF; nf++)
                    mma16816(acc + (mf * NF + nf) * 4, a[mf], b[nf]);
        }
    }
    __syncthreads();   // all warps done reading A before epilogue overwrites it
}

// bias + relu epilogue -> fp16 into A (width 256, rowB=512), swizzled
__device__ __forceinline__ void epilogue_relu(
    const float* acc, const float* __restrict__ bias, char* Asp)
{
    const int tid = threadIdx.x, lane = tid & 31, wid = tid >> 5;
    const int wm = wid >> 2, wn = wid & 3;
#pragma unroll
    for (int nf = 0; nf < 8; nf++) {
        int c = wn * 64 + nf * 8 + (lane & 3) * 2;
        float b0 = __ldg(bias + c), b1 = __ldg(bias + c + 1);
#pragma unroll
        for (int mf = 0; mf < 4; mf++) {
            const float* d = acc + (mf * 8 + nf) * 4;
            int r0 = wm * 64 + mf * 16 + (lane >> 2);
            int r1 = r0 + 8;
            float x0 = fmaxf(d[0] + b0, 0.f), x1 = fmaxf(d[1] + b1, 0.f);
            float x2 = fmaxf(d[2] + b0, 0.f), x3 = fmaxf(d[3] + b1, 0.f);
            __half2 p0 = __float22half2_rn(make_float2(x0, x1));
            __half2 p1 = __float22half2_rn(make_float2(x2, x3));
            uint32_t by0 = (uint32_t)(r0 * 512 + c * 2) ^ ((r0 & 7) << 4);
            uint32_t by1 = (uint32_t)(r1 * 512 + c * 2) ^ ((r1 & 7) << 4);
            *reinterpret_cast<uint32_t*>(Asp + by0) = h2_bits(p0);
            *reinterpret_cast<uint32_t*>(Asp + by1) = h2_bits(p1);
        }
    }
}

// ---------------------------------------------------------------------------
__global__ void __launch_bounds__(256, 1) mlp_kernel(
    const float* __restrict__ g,  const float* __restrict__ ns,
    const float* __restrict__ nr, const float* __restrict__ e,
    const int*   __restrict__ ei,
    const float* __restrict__ b1, const float* __restrict__ b2,
    const float* __restrict__ b3, const float* __restrict__ b4,
    int nEdges)
{
    extern __shared__ __align__(16) char smem[];
    char* Asp = smem;
    char* Bsp = smem + B_OFF;

    const int tid = threadIdx.x;
    const int m0  = blockIdx.x * 128;

    // ---- stage inputs: 128 rows x 512 fp16 (concat g|ns|nr|e), swizzled ----
#pragma unroll 4
    for (int i = 0; i < 32; i++) {
        int idx = tid + i * 256;           // 0..8191 chunk index
        int r   = idx >> 6;                // row 0..127
        int cc  = idx & 63;                // 16B chunk within row
        uint32_t byte = ((uint32_t)(r << 10) + (uint32_t)(cc << 4)) ^ ((r & 7) << 4);
        uint4 out4;
        int edge = m0 + r;
        if (edge < nEdges) {
            const float* base = (cc < 32) ? ((cc < 16) ? g : ns)
                                          : ((cc < 48) ? nr : e);
            int col0 = (cc & 15) << 3;
            const float4* p = reinterpret_cast<const float4*>(base + (size_t)edge * 128 + col0);
            float4 v0 = p[0], v1 = p[1];
            out4.x = h2_bits(__float22half2_rn(make_float2(v0.x, v0.y)));
            out4.y = h2_bits(__float22half2_rn(make_float2(v0.z, v0.w)));
            out4.z = h2_bits(__float22half2_rn(make_float2(v1.x, v1.y)));
            out4.w = h2_bits(__float22half2_rn(make_float2(v1.z, v1.w)));
        } else {
            out4 = make_uint4(0, 0, 0, 0);
        }
        *reinterpret_cast<uint4*>(Asp + byte) = out4;
    }
    // (run_gemm opens with __syncthreads)

    float acc[128];

    run_gemm<256, 8>(g_Wb + OFF_W1, 512, Asp, 1024, Bsp, acc);
    epilogue_relu(acc, b1, Asp);
    run_gemm<256, 8>(g_Wb + OFF_W2, 256, Asp, 512, Bsp, acc);
    epilogue_relu(acc, b2, Asp);
    run_gemm<256, 8>(g_Wb + OFF_W3, 256, Asp, 512, Bsp, acc);
    epilogue_relu(acc, b3, Asp);
    run_gemm<128, 4>(g_Wb + OFF_W4, 256, Asp, 512, Bsp, acc);

    // ---- L4 epilogue: +b4 (no relu), stage fp32 to smem (swizzled 16B) ----
    {
        const int lane = tid & 31, wid = tid >> 5;
        const int wm = wid >> 2, wn = wid & 3;
#pragma unroll
        for (int nf = 0; nf < 4; nf++) {
            int c = wn * 32 + nf * 8 + (lane & 3) * 2;
            float b0 = __ldg(b4 + c), b1v = __ldg(b4 + c + 1);
#pragma unroll
            for (int mf = 0; mf < 4; mf++) {
                const float* d = acc + (mf * 4 + nf) * 4;
                int r0 = wm * 64 + mf * 16 + (lane >> 2);
                int r1 = r0 + 8;
                uint32_t by0 = (uint32_t)(r0 * 512 + c * 4) ^ ((r0 & 7) << 4);
                uint32_t by1 = (uint32_t)(r1 * 512 + c * 4) ^ ((r1 & 7) << 4);
                *reinterpret_cast<float2*>(Asp + by0) = make_float2(d[0] + b0, d[1] + b1v);
                *reinterpret_cast<float2*>(Asp + by1) = make_float2(d[2] + b0, d[3] + b1v);
            }
        }
    }
    __syncthreads();

    // ---- vector-red segment sums: thread t handles row t/2, half t&1 ----
    {
        int lr   = tid >> 1;
        int half = tid & 1;
        int edge = m0 + lr;
        if (edge < nEdges) {
            int seg = ei[edge];
            float* dst = g_sums + (size_t)seg * FEAT + half * 64;
#pragma unroll
            for (int j = 0; j < 16; j++) {
                int c = half * 64 + j * 4;
                uint32_t byte = (uint32_t)(lr * 512 + c * 4) ^ ((lr & 7) << 4);
                float4 v = *reinterpret_cast<float4*>(Asp + byte);
                red4(dst + j * 4, v);
            }
        }
    }
}

// ---------------------------------------------------------------------------
__global__ void prep_kernel(const float* __restrict__ W1, const float* __restrict__ W2,
                            const float* __restrict__ W3, const float* __restrict__ W4)
{
    int i = blockIdx.x * blockDim.x + threadIdx.x;
    int stride = gridDim.x * blockDim.x;
    for (int idx = i; idx < W_TOTAL; idx += stride) {
        float v;
        if (idx < OFF_W2)      v = W1[idx];
        else if (idx < OFF_W3) v = W2[idx - OFF_W2];
        else if (idx < OFF_W4) v = W3[idx - OFF_W3];
        else                   v = W4[idx - OFF_W4];
        g_Wb[idx] = __float2half_rn(v);
    }
    for (int idx = i; idx < NSEG * FEAT; idx += stride) g_sums[idx] = 0.f;
    for (int idx = i; idx < NSEG; idx += stride) g_cnts[idx] = 0.f;
}

__global__ void count_kernel(const int* __restrict__ ei, int nEdges)
{
    int i = blockIdx.x * blockDim.x + threadIdx.x;
    if (i < nEdges) atomicAdd(&g_cnts[ei[i]], 1.0f);
}

__global__ void means_kernel()
{
    int i = blockIdx.x * blockDim.x + threadIdx.x;  // 131072 threads exactly
    g_means[i] = g_sums[i] / g_cnts[i >> 7];
}

__global__ void gather_kernel(const int* __restrict__ ei, float* __restrict__ out, int nEdges)
{
    int i = blockIdx.x * blockDim.x + threadIdx.x;   // one float4 per thread
    int total = nEdges * 32;
    if (i < total) {
        int edge = i >> 5;
        int c4   = i & 31;
        int seg  = __ldg(ei + edge);
        float4 v = *reinterpret_cast<const float4*>(g_means + (size_t)seg * FEAT + c4 * 4);
        reinterpret_cast<float4*>(out)[i] = v;
    }
}

// ---------------------------------------------------------------------------
extern "C" void kernel_launch(void* const* d_in, const int* in_sizes, int n_in,
                              void* d_out, int out_size)
{
    const float* g  = (const float*)d_in[0];
    const float* ns = (const float*)d_in[1];
    const float* nr = (const float*)d_in[2];
    const float* e  = (const float*)d_in[3];
    const int*   ei = (const int*)  d_in[4];
    const float* W1 = (const float*)d_in[5];
    const float* b1 = (const float*)d_in[6];
    const float* W2 = (const float*)d_in[7];
    const float* b2 = (const float*)d_in[8];
    const float* W3 = (const float*)d_in[9];
    const float* b3 = (const float*)d_in[10];
    const float* W4 = (const float*)d_in[11];
    const float* b4 = (const float*)d_in[12];
    float* out = (float*)d_out;

    const int nEdges = in_sizes[4];

    cudaFuncSetAttribute(mlp_kernel, cudaFuncAttributeMaxDynamicSharedMemorySize, SMEM_BYTES);

    prep_kernel<<<1152, 256>>>(W1, W2, W3, W4);
    count_kernel<<<(nEdges + 255) / 256, 256>>>(ei, nEdges);
    mlp_kernel<<<(nEdges + 127) / 128, 256, SMEM_BYTES>>>(g, ns, nr, e, ei,
                                                          b1, b2, b3, b4, nEdges);
    means_kernel<<<(NSEG * FEAT) / 256, 256>>>();
    gather_kernel<<<(nEdges * 32 + 255) / 256, 256>>>(ei, out, nEdges);
}

// round 14
// speedup vs baseline: 1.0023x; 1.0022x over previous
#include <cuda_runtime.h>
#include <cuda_fp16.h>
#include <cstdint>

// ---------------------------------------------------------------------------
// EdgeBlock: 4-layer MLP (512->256->256->256->128) per edge, segment mean over
// ei (1024 segments), gather means back per edge.
//
// FP16 compute (10 mantissa bits): weight-rounding error is correlated across
// the segment mean (doesn't average out), so weights need fp16, not bf16.
//
// Pipeline (5 launches, all graph-capturable):
//   1. prep_kernel    : convert W1..W4 fp32->fp16 into g_Wb, zero sums/counts
//   2. count_kernel   : histogram ei -> g_cnts (float)
//   3. mlp_kernel     : fused 4-layer fp16 tensor-core MLP per 128-edge tile,
//                       L4 output reduced into g_sums via red.global.add.v4.f32
//   4. means_kernel   : g_means = g_sums / g_cnts
//   5. gather_kernel  : out[i] = g_means[ei[i]]
// ---------------------------------------------------------------------------

#define NSEG   1024
#define FEAT   128
#define D_IN   512
#define HID    256

// weight offsets in elements within g_Wb
#define OFF_W1 0
#define OFF_W2 131072           // 512*256
#define OFF_W3 196608           // + 256*256
#define OFF_W4 262144           // + 256*256
#define W_TOTAL 294912          // + 256*128

__device__ __half g_Wb[W_TOTAL];
__device__ float g_sums[NSEG * FEAT];
__device__ float g_cnts[NSEG];
__device__ float g_means[NSEG * FEAT];

// ---------------- PTX helpers ----------------
__device__ __forceinline__ uint32_t smem_u32(const void* p) {
    return (uint32_t)__cvta_generic_to_shared(p);
}
__device__ __forceinline__ void ldsm4(uint32_t* d, uint32_t addr) {
    asm volatile("ldmatrix.sync.aligned.m8n8.x4.shared.b16 {%0,%1,%2,%3}, [%4];"
                 : "=r"(d[0]), "=r"(d[1]), "=r"(d[2]), "=r"(d[3]) : "r"(addr));
}
__device__ __forceinline__ void ldsm4t(uint32_t* d, uint32_t addr) {
    asm volatile("ldmatrix.sync.aligned.m8n8.x4.trans.shared.b16 {%0,%1,%2,%3}, [%4];"
                 : "=r"(d[0]), "=r"(d[1]), "=r"(d[2]), "=r"(d[3]) : "r"(addr));
}
__device__ __forceinline__ void mma16816(float* d, const uint32_t* a, const uint32_t* b) {
    asm volatile("mma.sync.aligned.m16n8k16.row.col.f32.f16.f16.f32 "
                 "{%0,%1,%2,%3}, {%4,%5,%6,%7}, {%8,%9}, {%0,%1,%2,%3};"
                 : "+f"(d[0]), "+f"(d[1]), "+f"(d[2]), "+f"(d[3])
                 : "r"(a[0]), "r"(a[1]), "r"(a[2]), "r"(a[3]),
                   "r"(b[0]), "r"(b[1]));
}
__device__ __forceinline__ void red4(float* p, float4 v) {
    asm volatile("red.global.add.v4.f32 [%0], {%1,%2,%3,%4};"
                 :: "l"(p), "f"(v.x), "f"(v.y), "f"(v.z), "f"(v.w) : "memory");
}
__device__ __forceinline__ uint32_t h2_bits(__half2 h) {
    return *reinterpret_cast<uint32_t*>(&h);
}

// SMEM layout (dynamic): activations A at [0, 131072), weight panel B at
// [131072, 163840). L4 fp32 staging reuses A's first 64 KB.
#define A_BYTES 131072
#define B_OFF   131072
#define SMEM_BYTES 163840

// ---------------------------------------------------------------------------
// Warp-tiled GEMM: M=128 (tile rows, in swizzled smem A, row stride rowBA),
// NTILE columns (weights [K][NTILE] fp16 row-major in global, streamed in
// 64-row panels to smem B), fp32 acc in registers.
// 8 warps: wm = wid>>2 (2 x 64 rows), wn = wid&3 (4 x NTILE/4 cols).
// NF = n-fragments per warp = NTILE/32.
// ---------------------------------------------------------------------------
template <int NTILE, int NF>
__device__ __forceinline__ void run_gemm(
    const __half* __restrict__ Wg, int K,
    char* Asp, int rowBA, char* Bsp, float* acc)
{
    const int tid  = threadIdx.x;
    const int lane = tid & 31;
    const int wid  = tid >> 5;
    const int wm   = wid >> 2;
    const int wn   = wid & 3;
    constexpr int BROWB = NTILE * 2;

    const uint32_t As = smem_u32(Asp);
    const uint32_t Bs = smem_u32(Bsp);

#pragma unroll
    for (int i = 0; i < 4 * NF * 4; i++) acc[i] = 0.f;

    for (int k0 = 0; k0 < K; k0 += 64) {
        __syncthreads();   // previous panel's reads (and prior A writes) done
        // ---- load 64 x NTILE fp16 weight panel into swizzled smem ----
        {
            constexpr int CHUNKS = 64 * NTILE / 8;      // 16B chunks
            const uint4* src = reinterpret_cast<const uint4*>(Wg + (size_t)k0 * NTILE);
#pragma unroll
            for (int i = 0; i < CHUNKS / 256; i++) {
                int idx = tid + i * 256;
                int kr  = idx / (NTILE / 8);
                int cc  = idx % (NTILE / 8);
                uint4 v = src[idx];
                uint32_t byte = (uint32_t)(kr * BROWB + cc * 16) ^ ((kr & 7) << 4);
                *reinterpret_cast<uint4*>(Bsp + byte) = v;
            }
        }
        __syncthreads();

#pragma unroll
        for (int kk = 0; kk < 64; kk += 16) {
            // ---- A fragments: 4 x m16k16 ----
            uint32_t a[4][4];
#pragma unroll
            for (int mf = 0; mf < 4; mf++) {
                int r = wm * 64 + mf * 16 + (lane & 15);
                uint32_t byte = (uint32_t)(r * rowBA + (((k0 + kk) >> 3) + (lane >> 4)) * 16);
                byte ^= (r & 7) << 4;
                ldsm4(a[mf], As + byte);
            }
            // ---- B fragments: NF x k16n8 via NF/2 trans loads ----
            uint32_t b[NF][2];
            {
                const int within = lane & 7;
                const int mat    = lane >> 3;
                const int kr     = kk + within + ((mat & 1) << 3);
                const uint32_t rowbase = (uint32_t)(kr * BROWB) ^ ((kr & 7) << 4);
#pragma unroll
                for (int p = 0; p < NF / 2; p++) {
                    int chunk = wn * NF + p * 2 + (mat >> 1);
                    uint32_t t[4];
                    ldsm4t(t, Bs + (rowbase ^ (uint32_t)(chunk * 16)));
                    b[2 * p][0] = t[0]; b[2 * p][1] = t[1];
                    b[2 * p + 1][0] = t[2]; b[2 * p + 1][1] = t[3];
                }
            }
#pragma unroll
            for (int mf = 0; mf < 4; mf++)
#pragma unroll
                for (int nf = 0; nf < NF; nf++)
                    mma16816(acc + (mf * NF + nf) * 4, a[mf], b[nf]);
        }
    }
    __syncthreads();   // all warps done reading A before epilogue overwrites it
}

// bias + relu epilogue -> fp16 into A (width 256, rowB=512), swizzled
__device__ __forceinline__ void epilogue_relu(
    const float* acc, const float* __restrict__ bias, char* Asp)
{
    const int tid = threadIdx.x, lane = tid & 31, wid = tid >> 5;
    const int wm = wid >> 2, wn = wid & 3;
#pragma unroll
    for (int nf = 0; nf < 8; nf++) {
        int c = wn * 64 + nf * 8 + (lane & 3) * 2;
        float b0 = __ldg(bias + c), b1 = __ldg(bias + c + 1);
#pragma unroll
        for (int mf = 0; mf < 4; mf++) {
            const float* d = acc + (mf * 8 + nf) * 4;
            int r0 = wm * 64 + mf * 16 + (lane >> 2);
            int r1 = r0 + 8;
            float x0 = fmaxf(d[0] + b0, 0.f), x1 = fmaxf(d[1] + b1, 0.f);
            float x2 = fmaxf(d[2] + b0, 0.f), x3 = fmaxf(d[3] + b1, 0.f);
            __half2 p0 = __float22half2_rn(make_float2(x0, x1));
            __half2 p1 = __float22half2_rn(make_float2(x2, x3));
            uint32_t by0 = (uint32_t)(r0 * 512 + c * 2) ^ ((r0 & 7) << 4);
            uint32_t by1 = (uint32_t)(r1 * 512 + c * 2) ^ ((r1 & 7) << 4);
            *reinterpret_cast<uint32_t*>(Asp + by0) = h2_bits(p0);
            *reinterpret_cast<uint32_t*>(Asp + by1) = h2_bits(p1);
        }
    }
}

// ---------------------------------------------------------------------------
__global__ void __launch_bounds__(256, 1) mlp_kernel(
    const float* __restrict__ g,  const float* __restrict__ ns,
    const float* __restrict__ nr, const float* __restrict__ e,
    const int*   __restrict__ ei,
    const float* __restrict__ b1, const float* __restrict__ b2,
    const float* __restrict__ b3, const float* __restrict__ b4,
    int nEdges)
{
    extern __shared__ __align__(16) char smem[];
    char* Asp = smem;
    char* Bsp = smem + B_OFF;

    const int tid = threadIdx.x;
    const int m0  = blockIdx.x * 128;

    // ---- stage inputs: 128 rows x 512 fp16 (concat g|ns|nr|e), swizzled ----
#pragma unroll 4
    for (int i = 0; i < 32; i++) {
        int idx = tid + i * 256;           // 0..8191 chunk index
        int r   = idx >> 6;                // row 0..127
        int cc  = idx & 63;                // 16B chunk within row
        uint32_t byte = ((uint32_t)(r << 10) + (uint32_t)(cc << 4)) ^ ((r & 7) << 4);
        uint4 out4;
        int edge = m0 + r;
        if (edge < nEdges) {
            const float* base = (cc < 32) ? ((cc < 16) ? g : ns)
                                          : ((cc < 48) ? nr : e);
            int col0 = (cc & 15) << 3;
            const float4* p = reinterpret_cast<const float4*>(base + (size_t)edge * 128 + col0);
            float4 v0 = p[0], v1 = p[1];
            out4.x = h2_bits(__float22half2_rn(make_float2(v0.x, v0.y)));
            out4.y = h2_bits(__float22half2_rn(make_float2(v0.z, v0.w)));
            out4.z = h2_bits(__float22half2_rn(make_float2(v1.x, v1.y)));
            out4.w = h2_bits(__float22half2_rn(make_float2(v1.z, v1.w)));
        } else {
            out4 = make_uint4(0, 0, 0, 0);
        }
        *reinterpret_cast<uint4*>(Asp + byte) = out4;
    }
    // (run_gemm opens with __syncthreads)

    float acc[128];

    run_gemm<256, 8>(g_Wb + OFF_W1, 512, Asp, 1024, Bsp, acc);
    epilogue_relu(acc, b1, Asp);
    run_gemm<256, 8>(g_Wb + OFF_W2, 256, Asp, 512, Bsp, acc);
    epilogue_relu(acc, b2, Asp);
    run_gemm<256, 8>(g_Wb + OFF_W3, 256, Asp, 512, Bsp, acc);
    epilogue_relu(acc, b3, Asp);
    run_gemm<128, 4>(g_Wb + OFF_W4, 256, Asp, 512, Bsp, acc);

    // ---- L4 epilogue: +b4 (no relu), stage fp32 to smem (swizzled 16B) ----
    {
        const int lane = tid & 31, wid = tid >> 5;
        const int wm = wid >> 2, wn = wid & 3;
#pragma unroll
        for (int nf = 0; nf < 4; nf++) {
            int c = wn * 32 + nf * 8 + (lane & 3) * 2;
            float b0 = __ldg(b4 + c), b1v = __ldg(b4 + c + 1);
#pragma unroll
            for (int mf = 0; mf < 4; mf++) {
                const float* d = acc + (mf * 4 + nf) * 4;
                int r0 = wm * 64 + mf * 16 + (lane >> 2);
                int r1 = r0 + 8;
                uint32_t by0 = (uint32_t)(r0 * 512 + c * 4) ^ ((r0 & 7) << 4);
                uint32_t by1 = (uint32_t)(r1 * 512 + c * 4) ^ ((r1 & 7) << 4);
                *reinterpret_cast<float2*>(Asp + by0) = make_float2(d[0] + b0, d[1] + b1v);
                *reinterpret_cast<float2*>(Asp + by1) = make_float2(d[2] + b0, d[3] + b1v);
            }
        }
    }
    __syncthreads();

    // ---- vector-red segment sums: thread t handles row t/2, half t&1 ----
    {
        int lr   = tid >> 1;
        int half = tid & 1;
        int edge = m0 + lr;
        if (edge < nEdges) {
            int seg = ei[edge];
            float* dst = g_sums + (size_t)seg * FEAT + half * 64;
#pragma unroll
            for (int j = 0; j < 16; j++) {
                int c = half * 64 + j * 4;
                uint32_t byte = (uint32_t)(lr * 512 + c * 4) ^ ((lr & 7) << 4);
                float4 v = *reinterpret_cast<float4*>(Asp + byte);
                red4(dst + j * 4, v);
            }
        }
    }
}

// ---------------------------------------------------------------------------
__global__ void prep_kernel(const float* __restrict__ W1, const float* __restrict__ W2,
                            const float* __restrict__ W3, const float* __restrict__ W4)
{
    int i = blockIdx.x * blockDim.x + threadIdx.x;
    int stride = gridDim.x * blockDim.x;
    for (int idx = i; idx < W_TOTAL; idx += stride) {
        float v;
        if (idx < OFF_W2)      v = W1[idx];
        else if (idx < OFF_W3) v = W2[idx - OFF_W2];
        else if (idx < OFF_W4) v = W3[idx - OFF_W3];
        else                   v = W4[idx - OFF_W4];
        g_Wb[idx] = __float2half_rn(v);
    }
    for (int idx = i; idx < NSEG * FEAT; idx += stride) g_sums[idx] = 0.f;
    for (int idx = i; idx < NSEG; idx += stride) g_cnts[idx] = 0.f;
}

__global__ void count_kernel(const int* __restrict__ ei, int nEdges)
{
    int i = blockIdx.x * blockDim.x + threadIdx.x;
    if (i < nEdges) atomicAdd(&g_cnts[ei[i]], 1.0f);
}

__global__ void means_kernel()
{
    int i = blockIdx.x * blockDim.x + threadIdx.x;  // 131072 threads exactly
    g_means[i] = g_sums[i] / g_cnts[i >> 7];
}

__global__ void gather_kernel(const int* __restrict__ ei, float* __restrict__ out, int nEdges)
{
    int i = blockIdx.x * blockDim.x + threadIdx.x;   // one float4 per thread
    int total = nEdges * 32;
    if (i < total) {
        int edge = i >> 5;
        int c4   = i & 31;
        int seg  = __ldg(ei + edge);
        float4 v = *reinterpret_cast<const float4*>(g_means + (size_t)seg * FEAT + c4 * 4);
        reinterpret_cast<float4*>(out)[i] = v;
    }
}

// ---------------------------------------------------------------------------
extern "C" void kernel_launch(void* const* d_in, const int* in_sizes, int n_in,
                              void* d_out, int out_size)
{
    const float* g  = (const float*)d_in[0];
    const float* ns = (const float*)d_in[1];
    const float* nr = (const float*)d_in[2];
    const float* e  = (const float*)d_in[3];
    const int*   ei = (const int*)  d_in[4];
    const float* W1 = (const float*)d_in[5];
    const float* b1 = (const float*)d_in[6];
    const float* W2 = (const float*)d_in[7];
    const float* b2 = (const float*)d_in[8];
    const float* W3 = (const float*)d_in[9];
    const float* b3 = (const float*)d_in[10];
    const float* W4 = (const float*)d_in[11];
    const float* b4 = (const float*)d_in[12];
    float* out = (float*)d_out;

    const int nEdges = in_sizes[4];

    cudaFuncSetAttribute(mlp_kernel, cudaFuncAttributeMaxDynamicSharedMemorySize, SMEM_BYTES);

    prep_kernel<<<1152, 256>>>(W1, W2, W3, W4);
    count_kernel<<<(nEdges + 255) / 256, 256>>>(ei, nEdges);
    mlp_kernel<<<(nEdges + 127) / 128, 256, SMEM_BYTES>>>(g, ns, nr, e, ei,
                                                          b1, b2, b3, b4, nEdges);
    means_kernel<<<(NSEG * FEAT) / 256, 256>>>();
    gather_kernel<<<(nEdges * 32 + 255) / 256, 256>>>(ei, out, nEdges);
}

// round 15
// speedup vs baseline: 1.0067x; 1.0043x over previous
#include <cuda_runtime.h>
#include <cuda_fp16.h>
#include <cstdint>

// ---------------------------------------------------------------------------
// EdgeBlock: 4-layer MLP (512->256->256->256->128) per edge, segment mean over
// ei (1024 segments), gather means back per edge.
//
// FP16 compute (10 mantissa bits): weight-rounding error is correlated across
// the segment mean (doesn't average out), so weights need fp16, not bf16.
//
// Pipeline (5 launches, all graph-capturable):
//   1. prep_kernel    : convert W1..W4 fp32->fp16 into g_Wb, zero sums/counts
//   2. count_kernel   : histogram ei -> g_cnts (float)
//   3. mlp_kernel     : fused 4-layer fp16 tensor-core MLP per 128-edge tile,
//                       L4 output reduced into g_sums via red.global.add.v4.f32
//   4. means_kernel   : g_means = g_sums / g_cnts
//   5. gather_kernel  : out[i] = g_means[ei[i]]
// ---------------------------------------------------------------------------

#define NSEG   1024
#define FEAT   128
#define D_IN   512
#define HID    256

// weight offsets in elements within g_Wb
#define OFF_W1 0
#define OFF_W2 131072           // 512*256
#define OFF_W3 196608           // + 256*256
#define OFF_W4 262144           // + 256*256
#define W_TOTAL 294912          // + 256*128

__device__ __half g_Wb[W_TOTAL];
__device__ float g_sums[NSEG * FEAT];
__device__ float g_cnts[NSEG];
__device__ float g_means[NSEG * FEAT];

// ---------------- PTX helpers ----------------
__device__ __forceinline__ uint32_t smem_u32(const void* p) {
    return (uint32_t)__cvta_generic_to_shared(p);
}
__device__ __forceinline__ void ldsm4(uint32_t* d, uint32_t addr) {
    asm volatile("ldmatrix.sync.aligned.m8n8.x4.shared.b16 {%0,%1,%2,%3}, [%4];"
                 : "=r"(d[0]), "=r"(d[1]), "=r"(d[2]), "=r"(d[3]) : "r"(addr));
}
__device__ __forceinline__ void ldsm4t(uint32_t* d, uint32_t addr) {
    asm volatile("ldmatrix.sync.aligned.m8n8.x4.trans.shared.b16 {%0,%1,%2,%3}, [%4];"
                 : "=r"(d[0]), "=r"(d[1]), "=r"(d[2]), "=r"(d[3]) : "r"(addr));
}
__device__ __forceinline__ void mma16816(float* d, const uint32_t* a, const uint32_t* b) {
    asm volatile("mma.sync.aligned.m16n8k16.row.col.f32.f16.f16.f32 "
                 "{%0,%1,%2,%3}, {%4,%5,%6,%7}, {%8,%9}, {%0,%1,%2,%3};"
                 : "+f"(d[0]), "+f"(d[1]), "+f"(d[2]), "+f"(d[3])
                 : "r"(a[0]), "r"(a[1]), "r"(a[2]), "r"(a[3]),
                   "r"(b[0]), "r"(b[1]));
}
__device__ __forceinline__ void red4(float* p, float4 v) {
    asm volatile("red.global.add.v4.f32 [%0], {%1,%2,%3,%4};"
                 :: "l"(p), "f"(v.x), "f"(v.y), "f"(v.z), "f"(v.w) : "memory");
}
__device__ __forceinline__ uint32_t h2_bits(__half2 h) {
    return *reinterpret_cast<uint32_t*>(&h);
}

// SMEM layout (dynamic): activations A at [0, 131072), weight panel B at
// [131072, 163840). L4 fp32 staging reuses A's first 64 KB.
#define A_BYTES 131072
#define B_OFF   131072
#define SMEM_BYTES 163840

// ---------------------------------------------------------------------------
// Warp-tiled GEMM: M=128 (tile rows, in swizzled smem A, row stride rowBA),
// NTILE columns (weights [K][NTILE] fp16 row-major in global, streamed in
// 64-row panels to smem B), fp32 acc in registers.
// 8 warps: wm = wid>>2 (2 x 64 rows), wn = wid&3 (4 x NTILE/4 cols).
// NF = n-fragments per warp = NTILE/32.
// ---------------------------------------------------------------------------
template <int NTILE, int NF>
__device__ __forceinline__ void run_gemm(
    const __half* __restrict__ Wg, int K,
    char* Asp, int rowBA, char* Bsp, float* acc)
{
    const int tid  = threadIdx.x;
    const int lane = tid & 31;
    const int wid  = tid >> 5;
    const int wm   = wid >> 2;
    const int wn   = wid & 3;
    constexpr int BROWB = NTILE * 2;

    const uint32_t As = smem_u32(Asp);
    const uint32_t Bs = smem_u32(Bsp);

#pragma unroll
    for (int i = 0; i < 4 * NF * 4; i++) acc[i] = 0.f;

    for (int k0 = 0; k0 < K; k0 += 64) {
        __syncthreads();   // previous panel's reads (and prior A writes) done
        // ---- load 64 x NTILE fp16 weight panel into swizzled smem ----
        {
            constexpr int CHUNKS = 64 * NTILE / 8;      // 16B chunks
            const uint4* src = reinterpret_cast<const uint4*>(Wg + (size_t)k0 * NTILE);
#pragma unroll
            for (int i = 0; i < CHUNKS / 256; i++) {
                int idx = tid + i * 256;
                int kr  = idx / (NTILE / 8);
                int cc  = idx % (NTILE / 8);
                uint4 v = src[idx];
                uint32_t byte = (uint32_t)(kr * BROWB + cc * 16) ^ ((kr & 7) << 4);
                *reinterpret_cast<uint4*>(Bsp + byte) = v;
            }
        }
        __syncthreads();

#pragma unroll
        for (int kk = 0; kk < 64; kk += 16) {
            // ---- A fragments: 4 x m16k16 ----
            uint32_t a[4][4];
#pragma unroll
            for (int mf = 0; mf < 4; mf++) {
                int r = wm * 64 + mf * 16 + (lane & 15);
                uint32_t byte = (uint32_t)(r * rowBA + (((k0 + kk) >> 3) + (lane >> 4)) * 16);
                byte ^= (r & 7) << 4;
                ldsm4(a[mf], As + byte);
            }
            // ---- B fragments: NF x k16n8 via NF/2 trans loads ----
            uint32_t b[NF][2];
            {
                const int within = lane & 7;
                const int mat    = lane >> 3;
                const int kr     = kk + within + ((mat & 1) << 3);
                const uint32_t rowbase = (uint32_t)(kr * BROWB) ^ ((kr & 7) << 4);
#pragma unroll
                for (int p = 0; p < NF / 2; p++) {
                    int chunk = wn * NF + p * 2 + (mat >> 1);
                    uint32_t t[4];
                    ldsm4t(t, Bs + (rowbase ^ (uint32_t)(chunk * 16)));
                    b[2 * p][0] = t[0]; b[2 * p][1] = t[1];
                    b[2 * p + 1][0] = t[2]; b[2 * p + 1][1] = t[3];
                }
            }
#pragma unroll
            for (int mf = 0; mf < 4; mf++)
#pragma unroll
                for (int nf = 0; nf < NF; nf++)
                    mma16816(acc + (mf * NF + nf) * 4, a[mf], b[nf]);
        }
    }
    __syncthreads();   // all warps done reading A before epilogue overwrites it
}

// bias + relu epilogue -> fp16 into A (width 256, rowB=512), swizzled
__device__ __forceinline__ void epilogue_relu(
    const float* acc, const float* __restrict__ bias, char* Asp)
{
    const int tid = threadIdx.x, lane = tid & 31, wid = tid >> 5;
    const int wm = wid >> 2, wn = wid & 3;
#pragma unroll
    for (int nf = 0; nf < 8; nf++) {
        int c = wn * 64 + nf * 8 + (lane & 3) * 2;
        float b0 = __ldg(bias + c), b1 = __ldg(bias + c + 1);
#pragma unroll
        for (int mf = 0; mf < 4; mf++) {
            const float* d = acc + (mf * 8 + nf) * 4;
            int r0 = wm * 64 + mf * 16 + (lane >> 2);
            int r1 = r0 + 8;
            float x0 = fmaxf(d[0] + b0, 0.f), x1 = fmaxf(d[1] + b1, 0.f);
            float x2 = fmaxf(d[2] + b0, 0.f), x3 = fmaxf(d[3] + b1, 0.f);
            __half2 p0 = __float22half2_rn(make_float2(x0, x1));
            __half2 p1 = __float22half2_rn(make_float2(x2, x3));
            uint32_t by0 = (uint32_t)(r0 * 512 + c * 2) ^ ((r0 & 7) << 4);
            uint32_t by1 = (uint32_t)(r1 * 512 + c * 2) ^ ((r1 & 7) << 4);
            *reinterpret_cast<uint32_t*>(Asp + by0) = h2_bits(p0);
            *reinterpret_cast<uint32_t*>(Asp + by1) = h2_bits(p1);
        }
    }
}

// ---------------------------------------------------------------------------
__global__ void __launch_bounds__(256, 1) mlp_kernel(
    const float* __restrict__ g,  const float* __restrict__ ns,
    const float* __restrict__ nr, const float* __restrict__ e,
    const int*   __restrict__ ei,
    const float* __restrict__ b1, const float* __restrict__ b2,
    const float* __restrict__ b3, const float* __restrict__ b4,
    int nEdges)
{
    extern __shared__ __align__(16) char smem[];
    char* Asp = smem;
    char* Bsp = smem + B_OFF;

    const int tid = threadIdx.x;
    const int m0  = blockIdx.x * 128;

    // ---- stage inputs: 128 rows x 512 fp16 (concat g|ns|nr|e), swizzled ----
#pragma unroll 4
    for (int i = 0; i < 32; i++) {
        int idx = tid + i * 256;           // 0..8191 chunk index
        int r   = idx >> 6;                // row 0..127
        int cc  = idx & 63;                // 16B chunk within row
        uint32_t byte = ((uint32_t)(r << 10) + (uint32_t)(cc << 4)) ^ ((r & 7) << 4);
        uint4 out4;
        int edge = m0 + r;
        if (edge < nEdges) {
            const float* base = (cc < 32) ? ((cc < 16) ? g : ns)
                                          : ((cc < 48) ? nr : e);
            int col0 = (cc & 15) << 3;
            const float4* p = reinterpret_cast<const float4*>(base + (size_t)edge * 128 + col0);
            float4 v0 = p[0], v1 = p[1];
            out4.x = h2_bits(__float22half2_rn(make_float2(v0.x, v0.y)));
            out4.y = h2_bits(__float22half2_rn(make_float2(v0.z, v0.w)));
            out4.z = h2_bits(__float22half2_rn(make_float2(v1.x, v1.y)));
            out4.w = h2_bits(__float22half2_rn(make_float2(v1.z, v1.w)));
        } else {
            out4 = make_uint4(0, 0, 0, 0);
        }
        *reinterpret_cast<uint4*>(Asp + byte) = out4;
    }
    // (run_gemm opens with __syncthreads)

    float acc[128];

    run_gemm<256, 8>(g_Wb + OFF_W1, 512, Asp, 1024, Bsp, acc);
    epilogue_relu(acc, b1, Asp);
    run_gemm<256, 8>(g_Wb + OFF_W2, 256, Asp, 512, Bsp, acc);
    epilogue_relu(acc, b2, Asp);
    run_gemm<256, 8>(g_Wb + OFF_W3, 256, Asp, 512, Bsp, acc);
    epilogue_relu(acc, b3, Asp);
    run_gemm<128, 4>(g_Wb + OFF_W4, 256, Asp, 512, Bsp, acc);

    // ---- L4 epilogue: +b4 (no relu), stage fp32 to smem (swizzled 16B) ----
    {
        const int lane = tid & 31, wid = tid >> 5;
        const int wm = wid >> 2, wn = wid & 3;
#pragma unroll
        for (int nf = 0; nf < 4; nf++) {
            int c = wn * 32 + nf * 8 + (lane & 3) * 2;
            float b0 = __ldg(b4 + c), b1v = __ldg(b4 + c + 1);
#pragma unroll
            for (int mf = 0; mf < 4; mf++) {
                const float* d = acc + (mf * 4 + nf) * 4;
                int r0 = wm * 64 + mf * 16 + (lane >> 2);
                int r1 = r0 + 8;
                uint32_t by0 = (uint32_t)(r0 * 512 + c * 4) ^ ((r0 & 7) << 4);
                uint32_t by1 = (uint32_t)(r1 * 512 + c * 4) ^ ((r1 & 7) << 4);
                *reinterpret_cast<float2*>(Asp + by0) = make_float2(d[0] + b0, d[1] + b1v);
                *reinterpret_cast<float2*>(Asp + by1) = make_float2(d[2] + b0, d[3] + b1v);
            }
        }
    }
    __syncthreads();

    // ---- vector-red segment sums: thread t handles row t/2, half t&1 ----
    {
        int lr   = tid >> 1;
        int half = tid & 1;
        int edge = m0 + lr;
        if (edge < nEdges) {
            int seg = ei[edge];
            float* dst = g_sums + (size_t)seg * FEAT + half * 64;
#pragma unroll
            for (int j = 0; j < 16; j++) {
                int c = half * 64 + j * 4;
                uint32_t byte = (uint32_t)(lr * 512 + c * 4) ^ ((lr & 7) << 4);
                float4 v = *reinterpret_cast<float4*>(Asp + byte);
                red4(dst + j * 4, v);
            }
        }
    }
}

// ---------------------------------------------------------------------------
__global__ void prep_kernel(const float* __restrict__ W1, const float* __restrict__ W2,
                            const float* __restrict__ W3, const float* __restrict__ W4)
{
    int i = blockIdx.x * blockDim.x + threadIdx.x;
    int stride = gridDim.x * blockDim.x;
    for (int idx = i; idx < W_TOTAL; idx += stride) {
        float v;
        if (idx < OFF_W2)      v = W1[idx];
        else if (idx < OFF_W3) v = W2[idx - OFF_W2];
        else if (idx < OFF_W4) v = W3[idx - OFF_W3];
        else                   v = W4[idx - OFF_W4];
        g_Wb[idx] = __float2half_rn(v);
    }
    for (int idx = i; idx < NSEG * FEAT; idx += stride) g_sums[idx] = 0.f;
    for (int idx = i; idx < NSEG; idx += stride) g_cnts[idx] = 0.f;
}

__global__ void count_kernel(const int* __restrict__ ei, int nEdges)
{
    int i = blockIdx.x * blockDim.x + threadIdx.x;
    if (i < nEdges) atomicAdd(&g_cnts[ei[i]], 1.0f);
}

__global__ void means_kernel()
{
    int i = blockIdx.x * blockDim.x + threadIdx.x;  // 131072 threads exactly
    g_means[i] = g_sums[i] / g_cnts[i >> 7];
}

__global__ void gather_kernel(const int* __restrict__ ei, float* __restrict__ out, int nEdges)
{
    int i = blockIdx.x * blockDim.x + threadIdx.x;   // one float4 per thread
    int total = nEdges * 32;
    if (i < total) {
        int edge = i >> 5;
        int c4   = i & 31;
        int seg  = __ldg(ei + edge);
        float4 v = *reinterpret_cast<const float4*>(g_means + (size_t)seg * FEAT + c4 * 4);
        reinterpret_cast<float4*>(out)[i] = v;
    }
}

// ---------------------------------------------------------------------------
extern "C" void kernel_launch(void* const* d_in, const int* in_sizes, int n_in,
                              void* d_out, int out_size)
{
    const float* g  = (const float*)d_in[0];
    const float* ns = (const float*)d_in[1];
    const float* nr = (const float*)d_in[2];
    const float* e  = (const float*)d_in[3];
    const int*   ei = (const int*)  d_in[4];
    const float* W1 = (const float*)d_in[5];
    const float* b1 = (const float*)d_in[6];
    const float* W2 = (const float*)d_in[7];
    const float* b2 = (const float*)d_in[8];
    const float* W3 = (const float*)d_in[9];
    const float* b3 = (const float*)d_in[10];
    const float* W4 = (const float*)d_in[11];
    const float* b4 = (const float*)d_in[12];
    float* out = (float*)d_out;

    const int nEdges = in_sizes[4];

    cudaFuncSetAttribute(mlp_kernel, cudaFuncAttributeMaxDynamicSharedMemorySize, SMEM_BYTES);

    prep_kernel<<<1152, 256>>>(W1, W2, W3, W4);
    count_kernel<<<(nEdges + 255) / 256, 256>>>(ei, nEdges);
    mlp_kernel<<<(nEdges + 127) / 128, 256, SMEM_BYTES>>>(g, ns, nr, e, ei,
                                                          b1, b2, b3, b4, nEdges);
    means_kernel<<<(NSEG * FEAT) / 256, 256>>>();
    gather_kernel<<<(nEdges * 32 + 255) / 256, 256>>>(ei, out, nEdges);
}